// round 5
// baseline (speedup 1.0000x reference)
#include <cuda_runtime.h>
#include <cuda_bf16.h>

// Problem constants
#define BB 4
#define SS 1024
#define DD 2048

// Scratch (allocation-free rule: __device__ globals)
__device__ float g_v[BB * DD];
__device__ float g_o[BB * DD];

// y[b][d] = sum_k x[b][k] * W[d][k] + bias[d]
// K-split x4: each output row is computed by 4 warps, each covering a
// K-quarter (512 floats). Block = 8 warps = 2 rows x 4 quarters.
// Grid = 1024 blocks -> 8192 warps (~86% occupancy vs 22% before).
// x (32 KB) is read through L1 (resident per-SM), no smem staging.
__device__ __forceinline__ void gemv4_body(const float* __restrict__ W,
                                           const float* __restrict__ x,
                                           const float* __restrict__ bias,
                                           float* __restrict__ y) {
    __shared__ float partial[2][4][BB];  // [row][quarter][batch]

    const int tid  = threadIdx.x;
    const int wid  = tid >> 5;          // 0..7
    const int lane = tid & 31;
    const int row_sub = wid >> 2;       // 0..1
    const int q       = wid & 3;        // K-quarter 0..3
    const int grow = blockIdx.x * 2 + row_sub;

    const float4* Wrow = (const float4*)(W + (size_t)grow * DD);
    const float4* x4   = (const float4*)x;

    const int kbase = q * (DD / 4 / 4) + lane;  // q*128 + lane, float4 units

    // Front-batch the 4 W float4s (independent LDGs, 16 regs).
    float4 w0 = Wrow[kbase];
    float4 w1 = Wrow[kbase + 32];
    float4 w2 = Wrow[kbase + 64];
    float4 w3 = Wrow[kbase + 96];

    float a0 = 0.f, a1 = 0.f, a2 = 0.f, a3 = 0.f;
    #pragma unroll
    for (int i = 0; i < 4; ++i) {
        const float4 ww = (i == 0) ? w0 : (i == 1) ? w1 : (i == 2) ? w2 : w3;
        const int k = kbase + i * 32;
        const float4 x0 = __ldg(&x4[0 * (DD / 4) + k]);
        const float4 x1 = __ldg(&x4[1 * (DD / 4) + k]);
        const float4 x2 = __ldg(&x4[2 * (DD / 4) + k]);
        const float4 x3 = __ldg(&x4[3 * (DD / 4) + k]);
        a0 += ww.x * x0.x + ww.y * x0.y + ww.z * x0.z + ww.w * x0.w;
        a1 += ww.x * x1.x + ww.y * x1.y + ww.z * x1.z + ww.w * x1.w;
        a2 += ww.x * x2.x + ww.y * x2.y + ww.z * x2.z + ww.w * x2.w;
        a3 += ww.x * x3.x + ww.y * x3.y + ww.z * x3.z + ww.w * x3.w;
    }
    #pragma unroll
    for (int off = 16; off > 0; off >>= 1) {
        a0 += __shfl_xor_sync(0xffffffffu, a0, off);
        a1 += __shfl_xor_sync(0xffffffffu, a1, off);
        a2 += __shfl_xor_sync(0xffffffffu, a2, off);
        a3 += __shfl_xor_sync(0xffffffffu, a3, off);
    }
    if (lane == 0) {
        partial[row_sub][q][0] = a0;
        partial[row_sub][q][1] = a1;
        partial[row_sub][q][2] = a2;
        partial[row_sub][q][3] = a3;
    }
    __syncthreads();

    // threads 0..7 combine quarters: t = row*4 + batch
    if (tid < 8) {
        const int r = tid >> 2;
        const int b = tid & 3;
        const int gr = blockIdx.x * 2 + r;
        const float s = partial[r][0][b] + partial[r][1][b] +
                        partial[r][2][b] + partial[r][3][b] + bias[gr];
        y[b * DD + gr] = s;
    }
}

// Stage 1: g_v = condition @ Wv^T + bv
__global__ __launch_bounds__(256) void gemv_v_kernel(const float* __restrict__ cond,
                                                     const float* __restrict__ Wv,
                                                     const float* __restrict__ bv) {
    gemv4_body(Wv, cond, bv, g_v);
}

// Stage 2: g_o = g_v @ Wo^T + bo
__global__ __launch_bounds__(256) void gemv_o_kernel(const float* __restrict__ Wo,
                                                     const float* __restrict__ bo) {
    gemv4_body(Wo, g_v, bo, g_o);
}

// Stage 3: out[b][s][:] = g_o[b][:]  for all s   (pure write bandwidth)
__global__ __launch_bounds__(256) void bcast_kernel(float4* __restrict__ out) {
    const int i4 = blockIdx.x * 256 + threadIdx.x;  // over BB*SS*DD/4 = 2M float4
    const int per_b = SS * DD / 4;                  // 524288
    const int b = i4 / per_b;
    const int d4 = i4 & (DD / 4 - 1);
    out[i4] = ((const float4*)g_o)[b * (DD / 4) + d4];
}

extern "C" void kernel_launch(void* const* d_in, const int* in_sizes, int n_in,
                              void* d_out, int out_size) {
    // Input order (metadata): hidden_states, condition, Wq, bq, Wk, bk, Wv, bv, Wo, bo
    const float* cond = (const float*)d_in[1];
    const float* Wv   = (const float*)d_in[6];
    const float* bv   = (const float*)d_in[7];
    const float* Wo   = (const float*)d_in[8];
    const float* bo   = (const float*)d_in[9];
    float* out = (float*)d_out;

    gemv_v_kernel<<<DD / 2, 256>>>(cond, Wv, bv);
    gemv_o_kernel<<<DD / 2, 256>>>(Wo, bo);
    bcast_kernel<<<(BB * SS * DD / 4) / 256, 256>>>((float4*)out);
}

// round 7
// speedup vs baseline: 1.0244x; 1.0244x over previous
#include <cuda_runtime.h>
#include <cuda_bf16.h>

#define BB 4
#define SS 1024
#define DD 2048
#define KSPLIT 4
#define KCHUNK (DD / KSPLIT)   // 512 floats per K-chunk
#define ROWTILE 32
#define NRG (DD / ROWTILE)     // 64 row groups

// K-split partials (allocation-free rule: __device__ globals).
// IMPORTANT: referenced ONLY from device code (host address-of a __device__
// symbol is invalid and was the R6 correctness bug).
__device__ float g_vp[KSPLIT][BB][DD];
__device__ float g_op[KSPLIT][BB][DD];

__device__ __forceinline__ float4 f4add(float4 a, float4 b) {
    return make_float4(a.x + b.x, a.y + b.y, a.z + b.z, a.w + b.w);
}

// Partial GEMV with 8-row register blocking.
// Block = 256 thr = 8 warps; block handles 32 rows x one 512-float K-chunk.
// Warp (rw,kw): rows rg*32+rw*8..+8, k-half kw (64 float4 each).
// STAGE 0: x = cond (global), writes g_vp (no bias).
// STAGE 1: x = sum_kc g_vp + bv (staged), writes g_op (bo added in bcast).
template<int STAGE>
__global__ __launch_bounds__(256, 2) void gemv_partial(
    const float* __restrict__ W,
    const float* __restrict__ xg)   // cond (stage0) or bv (stage1)
{
    __shared__ float xs[BB][KCHUNK];   // 8 KB
    __shared__ float pr[8][ROWTILE];   // per-warp reduced outputs

    float* __restrict__ yp = (STAGE == 0) ? &g_vp[0][0][0] : &g_op[0][0][0];

    const int bid = blockIdx.x;
    const int kc  = bid & (KSPLIT - 1);
    const int rg  = bid >> 2;
    const int tid = threadIdx.x;

    // Stage x chunk into shared memory.
    for (int i = tid; i < BB * KCHUNK; i += 256) {
        const int b = i >> 9;            // / KCHUNK
        const int k = i & (KCHUNK - 1);
        if (STAGE == 0) {
            xs[b][k] = xg[b * DD + kc * KCHUNK + k];
        } else {
            const int gk = kc * KCHUNK + k;
            xs[b][k] = g_vp[0][b][gk] + g_vp[1][b][gk] +
                       g_vp[2][b][gk] + g_vp[3][b][gk] + xg[gk];
        }
    }
    __syncthreads();

    const int wid  = tid >> 5;
    const int lane = tid & 31;
    const int rw   = wid >> 1;          // 0..3
    const int kw   = wid & 1;           // 0..1
    const int r0   = rg * ROWTILE + rw * 8;

    float acc[32];
    #pragma unroll
    for (int i = 0; i < 32; ++i) acc[i] = 0.f;

    const float4* xs0 = (const float4*)xs[0];
    const float4* xs1 = (const float4*)xs[1];
    const float4* xs2 = (const float4*)xs[2];
    const float4* xs3 = (const float4*)xs[3];

    #pragma unroll
    for (int step = 0; step < 2; ++step) {
        const int k4 = kw * 64 + step * 32 + lane;       // within chunk (0..127)
        const float4* Wb = (const float4*)W + (size_t)(kc * (KCHUNK / 4)) + k4;

        float4 w[8];
        #pragma unroll
        for (int r = 0; r < 8; ++r)
            w[r] = Wb[(size_t)(r0 + r) * (DD / 4)];      // 8 independent LDG.128

        const float4 x0 = xs0[k4];
        const float4 x1 = xs1[k4];
        const float4 x2 = xs2[k4];
        const float4 x3 = xs3[k4];

        #pragma unroll
        for (int r = 0; r < 8; ++r) {
            acc[r * 4 + 0] += w[r].x * x0.x + w[r].y * x0.y + w[r].z * x0.z + w[r].w * x0.w;
            acc[r * 4 + 1] += w[r].x * x1.x + w[r].y * x1.y + w[r].z * x1.z + w[r].w * x1.w;
            acc[r * 4 + 2] += w[r].x * x2.x + w[r].y * x2.y + w[r].z * x2.z + w[r].w * x2.w;
            acc[r * 4 + 3] += w[r].x * x3.x + w[r].y * x3.y + w[r].z * x3.z + w[r].w * x3.w;
        }
    }

    // Butterfly reduce: 32 values/lane -> 1 value/lane.
    // After 5 steps lane l holds the full sum for output l (row r0+(l>>2), batch l&3).
    int L = 32;
    #pragma unroll
    for (int m = 16; m >= 1; m >>= 1) {
        L >>= 1;
        const bool up = (lane & m) != 0;
        #pragma unroll
        for (int j = 0; j < L; ++j) {
            const float send = up ? acc[j] : acc[j + L];
            const float recv = __shfl_xor_sync(0xffffffffu, send, m);
            acc[j] = (up ? acc[j + L] : acc[j]) + recv;
        }
    }

    pr[wid][lane] = acc[0];
    __syncthreads();

    // Combine the two kw halves and write partials.
    if (tid < 128) {
        const int rw2 = tid >> 5;
        const int l   = tid & 31;
        const float s = pr[rw2 * 2][l] + pr[rw2 * 2 + 1][l];
        const int row = rg * ROWTILE + rw2 * 8 + (l >> 2);
        const int b   = l & 3;
        yp[((size_t)kc * BB + b) * DD + row] = s;
    }
}

// out[b][s][:] = (sum_kc g_op[kc][b][:]) + bo, broadcast over s.
// Each thread owns one (b, d4) and writes 8 s-positions (loads amortized 8x).
__global__ __launch_bounds__(256) void bcast_kernel(float4* __restrict__ out,
                                                    const float* __restrict__ bo) {
    const int t  = blockIdx.x * 256 + threadIdx.x;   // 256K threads
    const int d4 = t & 511;
    const int g  = t >> 9;
    const int b  = g >> 7;           // 0..3
    const int s8 = (g & 127) * 8;    // s base

    const float4* op  = (const float4*)g_op;         // [kc][b][512 f4]
    const float4* bo4 = (const float4*)bo;
    float4 o = f4add(f4add(op[(0 * BB + b) * 512 + d4], op[(1 * BB + b) * 512 + d4]),
                     f4add(op[(2 * BB + b) * 512 + d4], op[(3 * BB + b) * 512 + d4]));
    o = f4add(o, bo4[d4]);

    float4* dst = out + ((size_t)(b * SS + s8) * 512) + d4;
    #pragma unroll
    for (int i = 0; i < 8; ++i)
        dst[(size_t)i * 512] = o;
}

extern "C" void kernel_launch(void* const* d_in, const int* in_sizes, int n_in,
                              void* d_out, int out_size) {
    // Inputs: hidden_states, condition, Wq, bq, Wk, bk, Wv, bv, Wo, bo
    const float* cond = (const float*)d_in[1];
    const float* bv   = (const float*)d_in[7];
    const float* Wv   = (const float*)d_in[6];
    const float* Wo   = (const float*)d_in[8];
    const float* bo   = (const float*)d_in[9];
    float* out = (float*)d_out;

    gemv_partial<0><<<NRG * KSPLIT, 256>>>(Wv, cond);
    gemv_partial<1><<<NRG * KSPLIT, 256>>>(Wo, bv);
    bcast_kernel<<<(BB * SS * (DD / 4) / 8) / 256, 256>>>((float4*)out, bo);
}